// round 2
// baseline (speedup 1.0000x reference)
#include <cuda_runtime.h>
#include <math.h>

#define B 8
#define L 4096
#define H 16
#define E 64
#define BH (B*H)
#define EPSF 1e-6f
#define NEG_CLAMP -20.0f

#define P1_SPLIT 4
#define P1_CHUNK (L/P1_SPLIT)   // 1024 tokens per block
#define TILE_T 16               // tokens per shared tile

#define P2_SPLIT 4
#define P2_CHUNK (L/P2_SPLIT)

// Scratch (no cudaMalloc allowed): per-(b,h) kv outer-product accumulator and k-sum.
__device__ float g_kv[BH*E*E];    // 2 MB
__device__ float g_ksum[BH*E];    // 32 KB

__global__ void zero_scratch_kernel() {
    int i = blockIdx.x*blockDim.x + threadIdx.x;
    if (i < BH*E*E) g_kv[i] = 0.0f;
    if (i < BH*E)   g_ksum[i] = 0.0f;
}

__device__ __forceinline__ float soft_logit_exp(float x, float inv_temp) {
    float v = (x < 0.0f) ? NEG_CLAMP : x;
    return __expf(v * inv_temp);
}

// ---------------------------------------------------------------------------
// Phase 1: kv[bh][d][e] += sum_l softmax(k)[l][d] * v[l][e];  ksum[bh][d] += ...
// grid (BH, P1_SPLIT), 256 threads.
// Thread roles: load phase: tid = tokg*16 + lane (16 tokens x 16 lanes, 4 elems/lane)
//               accum phase: d-group = tid>>4 (4 rows), e-group = tid&15 (4 cols)
// ---------------------------------------------------------------------------
__global__ __launch_bounds__(256, 1)
void phase1_kernel(const float* __restrict__ keys,
                   const float* __restrict__ values,
                   const float* __restrict__ delta1) {
    __shared__ float k_sm[TILE_T][E];
    __shared__ float v_sm[TILE_T][E];
    __shared__ float ksum_sm[E];

    const int bh    = blockIdx.x;
    const int split = blockIdx.y;
    const int b = bh >> 4;
    const int h = bh & 15;
    const int tid  = threadIdx.x;
    const int lane = tid & 15;     // e-quad index
    const int tokg = tid >> 4;     // token-in-tile (load) / d-quad (accum)

    const float inv_temp = 1.0f / log1pf(__expf(delta1[0]));

    if (tid < E) ksum_sm[tid] = 0.0f;

    float acc[4][4];
    #pragma unroll
    for (int i = 0; i < 4; i++)
        #pragma unroll
        for (int j = 0; j < 4; j++) acc[i][j] = 0.0f;
    float ksl[4] = {0.f, 0.f, 0.f, 0.f};

    const int l0 = split * P1_CHUNK;
    const int d0 = tokg * 4;
    const int e0 = lane * 4;

    for (int tile = 0; tile < P1_CHUNK / TILE_T; tile++) {
        // ---- load + softmax(k) for 16 tokens ----
        const int l = l0 + tile * TILE_T + tokg;
        const size_t off = ((size_t)(b * L + l) * H + h) * E + (size_t)(lane * 4);
        float4 kk = *(const float4*)(keys + off);
        float4 vv = *(const float4*)(values + off);

        float x0 = soft_logit_exp(kk.x, inv_temp);
        float x1 = soft_logit_exp(kk.y, inv_temp);
        float x2 = soft_logit_exp(kk.z, inv_temp);
        float x3 = soft_logit_exp(kk.w, inv_temp);
        float s = x0 + x1 + x2 + x3;
        #pragma unroll
        for (int m = 8; m >= 1; m >>= 1)
            s += __shfl_xor_sync(0xffffffffu, s, m, 16);
        float inv = 1.0f / s;
        x0 *= inv; x1 *= inv; x2 *= inv; x3 *= inv;

        k_sm[tokg][lane*4+0] = x0;
        k_sm[tokg][lane*4+1] = x1;
        k_sm[tokg][lane*4+2] = x2;
        k_sm[tokg][lane*4+3] = x3;
        *(float4*)&v_sm[tokg][lane*4] = vv;

        ksl[0] += x0; ksl[1] += x1; ksl[2] += x2; ksl[3] += x3;
        __syncthreads();

        // ---- accumulate 4x4 outer-product tile over 16 tokens ----
        #pragma unroll
        for (int t = 0; t < TILE_T; t++) {
            float4 kd = *(const float4*)&k_sm[t][d0];  // broadcast within 16-lane group
            float4 ve = *(const float4*)&v_sm[t][e0];
            acc[0][0] = fmaf(kd.x, ve.x, acc[0][0]);
            acc[0][1] = fmaf(kd.x, ve.y, acc[0][1]);
            acc[0][2] = fmaf(kd.x, ve.z, acc[0][2]);
            acc[0][3] = fmaf(kd.x, ve.w, acc[0][3]);
            acc[1][0] = fmaf(kd.y, ve.x, acc[1][0]);
            acc[1][1] = fmaf(kd.y, ve.y, acc[1][1]);
            acc[1][2] = fmaf(kd.y, ve.z, acc[1][2]);
            acc[1][3] = fmaf(kd.y, ve.w, acc[1][3]);
            acc[2][0] = fmaf(kd.z, ve.x, acc[2][0]);
            acc[2][1] = fmaf(kd.z, ve.y, acc[2][1]);
            acc[2][2] = fmaf(kd.z, ve.z, acc[2][2]);
            acc[2][3] = fmaf(kd.z, ve.w, acc[2][3]);
            acc[3][0] = fmaf(kd.w, ve.x, acc[3][0]);
            acc[3][1] = fmaf(kd.w, ve.y, acc[3][1]);
            acc[3][2] = fmaf(kd.w, ve.z, acc[3][2]);
            acc[3][3] = fmaf(kd.w, ve.w, acc[3][3]);
        }
        __syncthreads();
    }

    // ---- flush ksum ----
    atomicAdd(&ksum_sm[lane*4+0], ksl[0]);
    atomicAdd(&ksum_sm[lane*4+1], ksl[1]);
    atomicAdd(&ksum_sm[lane*4+2], ksl[2]);
    atomicAdd(&ksum_sm[lane*4+3], ksl[3]);
    __syncthreads();
    if (tid < E) atomicAdd(&g_ksum[bh*E + tid], ksum_sm[tid]);

    // ---- flush kv partials ----
    float* kvb = g_kv + (size_t)bh * E * E;
    #pragma unroll
    for (int i = 0; i < 4; i++)
        #pragma unroll
        for (int j = 0; j < 4; j++)
            atomicAdd(&kvb[(d0 + i) * E + (e0 + j)], acc[i][j]);
}

// ---------------------------------------------------------------------------
// Phase 2: out[b,l,h,d] = z_l * sum_e softmax(q)[l,e] * kv[e,d]
// grid (BH, P2_SPLIT), 256 threads = 16 tokens x 16 lanes per tile.
// ---------------------------------------------------------------------------
__global__ __launch_bounds__(256, 1)
void phase2_kernel(const float* __restrict__ queries,
                   const float* __restrict__ delta1,
                   float* __restrict__ out) {
    __shared__ float kv_sm[E][E];     // 16 KB
    __shared__ float ksum_sm[E];
    __shared__ float q_sm[TILE_T][E]; // 4 KB

    const int bh    = blockIdx.x;
    const int split = blockIdx.y;
    const int b = bh >> 4;
    const int h = bh & 15;
    const int tid  = threadIdx.x;
    const int lane = tid & 15;
    const int tokg = tid >> 4;

    const float inv_temp = 1.0f / log1pf(__expf(delta1[0]));

    // load kv + ksum into shared (coalesced float4)
    {
        const float4* src = (const float4*)(g_kv + (size_t)bh * E * E);
        float4* dst = (float4*)&kv_sm[0][0];
        for (int i = tid; i < E*E/4; i += 256) dst[i] = src[i];
        if (tid < E) ksum_sm[tid] = g_ksum[bh*E + tid];
    }
    __syncthreads();

    const int l0 = split * P2_CHUNK;
    const int d0 = lane * 4;

    for (int tile = 0; tile < P2_CHUNK / TILE_T; tile++) {
        const int l = l0 + tile * TILE_T + tokg;
        const size_t off = ((size_t)(b * L + l) * H + h) * E + (size_t)(lane * 4);
        float4 qq = *(const float4*)(queries + off);

        float q0 = soft_logit_exp(qq.x, inv_temp);
        float q1 = soft_logit_exp(qq.y, inv_temp);
        float q2 = soft_logit_exp(qq.z, inv_temp);
        float q3 = soft_logit_exp(qq.w, inv_temp);
        float s = q0 + q1 + q2 + q3;
        #pragma unroll
        for (int m = 8; m >= 1; m >>= 1)
            s += __shfl_xor_sync(0xffffffffu, s, m, 16);
        float inv = 1.0f / s;
        q0 *= inv; q1 *= inv; q2 *= inv; q3 *= inv;

        // z = 1/(q . ksum + eps)
        float zd = q0 * ksum_sm[lane*4+0] + q1 * ksum_sm[lane*4+1]
                 + q2 * ksum_sm[lane*4+2] + q3 * ksum_sm[lane*4+3];
        #pragma unroll
        for (int m = 8; m >= 1; m >>= 1)
            zd += __shfl_xor_sync(0xffffffffu, zd, m, 16);
        float z = 1.0f / (zd + EPSF);

        q_sm[tokg][lane*4+0] = q0;
        q_sm[tokg][lane*4+1] = q1;
        q_sm[tokg][lane*4+2] = q2;
        q_sm[tokg][lane*4+3] = q3;
        __syncwarp();

        float o0 = 0.f, o1 = 0.f, o2 = 0.f, o3 = 0.f;
        #pragma unroll 8
        for (int e = 0; e < E; e++) {
            float qe = q_sm[tokg][e];                    // broadcast
            float4 kvv = *(const float4*)&kv_sm[e][d0];  // conflict-free 256B row
            o0 = fmaf(qe, kvv.x, o0);
            o1 = fmaf(qe, kvv.y, o1);
            o2 = fmaf(qe, kvv.z, o2);
            o3 = fmaf(qe, kvv.w, o3);
        }
        float4 res = make_float4(o0*z, o1*z, o2*z, o3*z);
        *(float4*)(out + off) = res;
        __syncwarp();   // protect q_sm[tokg] reuse next tile
    }
}

extern "C" void kernel_launch(void* const* d_in, const int* in_sizes, int n_in,
                              void* d_out, int out_size) {
    const float* queries = (const float*)d_in[0];
    const float* keys    = (const float*)d_in[1];
    const float* values  = (const float*)d_in[2];
    const float* delta1  = (const float*)d_in[3];
    float* out = (float*)d_out;

    (void)in_sizes; (void)n_in; (void)out_size;

    zero_scratch_kernel<<<(BH*E*E + 255)/256, 256>>>();
    phase1_kernel<<<dim3(BH, P1_SPLIT), 256>>>(keys, values, delta1);
    phase2_kernel<<<dim3(BH, P2_SPLIT), 256>>>(queries, delta1, out);
}

// round 4
// speedup vs baseline: 1.1890x; 1.1890x over previous
#include <cuda_runtime.h>
#include <math.h>

typedef unsigned long long ull;

#define B 8
#define L 4096
#define H 16
#define E 64
#define BH (B*H)
#define EPSF 1e-6f
#define NEG_CLAMP -20.0f

#define P1_SPLIT 8
#define P1_CHUNK (L/P1_SPLIT)   // 512 tokens per block
#define TILE1 32

#define P2_SPLIT 8
#define P2_CHUNK (L/P2_SPLIT)   // 512 tokens per block
#define TILE2 32

// Scratch (no cudaMalloc allowed)
__device__ float g_kv[BH*E*E];    // 2 MB
__device__ float g_ksum[BH*E];    // 32 KB

__global__ void zero_scratch_kernel() {
    int i = blockIdx.x*blockDim.x + threadIdx.x;
    if (i < BH*E*E) g_kv[i] = 0.0f;
    if (i < BH*E)   g_ksum[i] = 0.0f;
}

__device__ __forceinline__ float soft_logit_exp(float x, float inv_temp) {
    float v = (x < 0.0f) ? NEG_CLAMP : x;
    return __expf(v * inv_temp);
}

// packed-f32x2 helpers
#define FFMA2(d,a,b,c) asm("fma.rn.f32x2 %0, %1, %2, %3;" : "=l"(d) : "l"(a), "l"(b), "l"(c))
__device__ __forceinline__ ull dup2(float x) {
    unsigned u = __float_as_uint(x);
    return (ull)u | ((ull)u << 32);
}
__device__ __forceinline__ float lo_f(ull u) { return __uint_as_float((unsigned)u); }
__device__ __forceinline__ float hi_f(ull u) { return __uint_as_float((unsigned)(u >> 32)); }

// ---------------------------------------------------------------------------
// Phase 1: kv[bh][d][e] = sum_l softmax(k)[l][d] * v[l][e];  ksum[bh][d]
// grid (BH, P1_SPLIT), 256 threads.
// Load map:  tok8 = tid>>3 (32 tokens/tile), lane8 = tid&7 (8 elems each)
// Accum map: tokg = tid>>4 -> d-quad, lane16 = tid&15 -> e-quad
// f32x2 halves = e-pairs; k stored pre-duplicated {k,k}.
// ---------------------------------------------------------------------------
__global__ __launch_bounds__(256, 1)
void phase1_kernel(const float* __restrict__ keys,
                   const float* __restrict__ values,
                   const float* __restrict__ delta1) {
    __shared__ __align__(16) float2 k_dup[TILE1][E];   // 16 KB, {k,k} duplicated (row = 512 B)
    __shared__ __align__(16) float  v_sm[TILE1][E];    // 8 KB (row = 256 B)
    __shared__ float  ksum_sm[E];

    const int bh    = blockIdx.x;
    const int split = blockIdx.y;
    const int b = bh >> 4;
    const int h = bh & 15;
    const int tid   = threadIdx.x;
    const int lane8 = tid & 7;
    const int tok8  = tid >> 3;
    const int lane16 = tid & 15;
    const int tokg   = tid >> 4;
    const int d0 = tokg * 4;
    const int e0 = lane16 * 4;

    const float inv_temp = 1.0f / log1pf(__expf(delta1[0]));

    if (tid < E) ksum_sm[tid] = 0.0f;

    ull acc[4][2];
    #pragma unroll
    for (int i = 0; i < 4; i++) { acc[i][0] = 0ull; acc[i][1] = 0ull; }
    float ksl[8];
    #pragma unroll
    for (int j = 0; j < 8; j++) ksl[j] = 0.0f;

    const int l0 = split * P1_CHUNK;

    for (int tile = 0; tile < P1_CHUNK / TILE1; tile++) {
        // ---- load + softmax(k) for 32 tokens (8 elems/thread) ----
        const int l = l0 + tile * TILE1 + tok8;
        const size_t off = ((size_t)(b * L + l) * H + h) * E + (size_t)(lane8 * 8);
        float4 ka4 = *(const float4*)(keys + off);
        float4 kb4 = *(const float4*)(keys + off + 4);
        float4 va4 = *(const float4*)(values + off);
        float4 vb4 = *(const float4*)(values + off + 4);

        float x[8];
        x[0] = soft_logit_exp(ka4.x, inv_temp);
        x[1] = soft_logit_exp(ka4.y, inv_temp);
        x[2] = soft_logit_exp(ka4.z, inv_temp);
        x[3] = soft_logit_exp(ka4.w, inv_temp);
        x[4] = soft_logit_exp(kb4.x, inv_temp);
        x[5] = soft_logit_exp(kb4.y, inv_temp);
        x[6] = soft_logit_exp(kb4.z, inv_temp);
        x[7] = soft_logit_exp(kb4.w, inv_temp);
        float s = ((x[0]+x[1]) + (x[2]+x[3])) + ((x[4]+x[5]) + (x[6]+x[7]));
        #pragma unroll
        for (int m = 4; m >= 1; m >>= 1)
            s += __shfl_xor_sync(0xffffffffu, s, m, 8);
        float inv = 1.0f / s;
        #pragma unroll
        for (int j = 0; j < 8; j++) { x[j] *= inv; ksl[j] += x[j]; }

        // base offset = tok8*512 + lane8*64 -> 16B aligned given 16B base
        ulonglong2* kd = (ulonglong2*)&k_dup[tok8][lane8 * 8];
        kd[0] = make_ulonglong2(dup2(x[0]), dup2(x[1]));
        kd[1] = make_ulonglong2(dup2(x[2]), dup2(x[3]));
        kd[2] = make_ulonglong2(dup2(x[4]), dup2(x[5]));
        kd[3] = make_ulonglong2(dup2(x[6]), dup2(x[7]));
        *(float4*)&v_sm[tok8][lane8 * 8]     = va4;
        *(float4*)&v_sm[tok8][lane8 * 8 + 4] = vb4;
        __syncthreads();

        // ---- accumulate 4x4 tile (as 4x2 f32x2) over 32 tokens ----
        #pragma unroll 4
        for (int t = 0; t < TILE1; t++) {
            const ulonglong2 ka = *(const ulonglong2*)&k_dup[t][d0];      // {k_d0,k_d0},{k_d1,k_d1}
            const ulonglong2 kb = *(const ulonglong2*)&k_dup[t][d0 + 2];  // d2, d3
            const ulonglong2 vv = *(const ulonglong2*)&v_sm[t][e0];       // {v_e0,v_e1},{v_e2,v_e3}
            FFMA2(acc[0][0], ka.x, vv.x, acc[0][0]);
            FFMA2(acc[0][1], ka.x, vv.y, acc[0][1]);
            FFMA2(acc[1][0], ka.y, vv.x, acc[1][0]);
            FFMA2(acc[1][1], ka.y, vv.y, acc[1][1]);
            FFMA2(acc[2][0], kb.x, vv.x, acc[2][0]);
            FFMA2(acc[2][1], kb.x, vv.y, acc[2][1]);
            FFMA2(acc[3][0], kb.y, vv.x, acc[3][0]);
            FFMA2(acc[3][1], kb.y, vv.y, acc[3][1]);
        }
        __syncthreads();
    }

    // ---- flush ksum: reduce 4 token-groups sharing same d within warp ----
    #pragma unroll
    for (int j = 0; j < 8; j++) {
        float v = ksl[j];
        v += __shfl_xor_sync(0xffffffffu, v, 8);
        v += __shfl_xor_sync(0xffffffffu, v, 16);
        if ((tid & 24) == 0) atomicAdd(&ksum_sm[lane8 * 8 + j], v);
    }
    __syncthreads();
    if (tid < E) atomicAdd(&g_ksum[bh * E + tid], ksum_sm[tid]);

    // ---- flush kv partials ----
    float* kvb = g_kv + (size_t)bh * E * E;
    #pragma unroll
    for (int i = 0; i < 4; i++) {
        #pragma unroll
        for (int jp = 0; jp < 2; jp++) {
            atomicAdd(&kvb[(d0 + i) * E + e0 + 2 * jp],     lo_f(acc[i][jp]));
            atomicAdd(&kvb[(d0 + i) * E + e0 + 2 * jp + 1], hi_f(acc[i][jp]));
        }
    }
}

// ---------------------------------------------------------------------------
// Phase 2: out[b,l,h,d] = z_l * sum_e softmax(q)[l,e] * kv[e,d]
// grid (BH, P2_SPLIT), 256 threads. 32 tokens/tile.
// Load map:  tok8 = tid>>3, lane8 = tid&7 (8 elems)
// GEMV map:  tp = tid>>4 -> tokens {2tp, 2tp+1}, lane16 = tid&15 -> d-quad
// f32x2 halves = d-pairs; q stored pre-duplicated. Mainloop is warp-local
// (producers/consumers of each token share a warp) -> __syncwarp only.
// ---------------------------------------------------------------------------
__global__ __launch_bounds__(256, 1)
void phase2_kernel(const float* __restrict__ queries,
                   const float* __restrict__ delta1,
                   float* __restrict__ out) {
    __shared__ __align__(16) float  kv_sm[E][E];          // 16 KB
    __shared__ __align__(16) float2 q_dup[TILE2][E + 2];  // pad 2 -> row = 528 B (16B-aligned)
    __shared__ float  ksum_sm[E];
    __shared__ float  z_sm[TILE2];

    const int bh    = blockIdx.x;
    const int split = blockIdx.y;
    const int b = bh >> 4;
    const int h = bh & 15;
    const int tid   = threadIdx.x;
    const int lane8 = tid & 7;
    const int tok8  = tid >> 3;
    const int lane16 = tid & 15;
    const int tp     = tid >> 4;
    const int d0 = lane16 * 4;

    const float inv_temp = 1.0f / log1pf(__expf(delta1[0]));

    {   // load kv + ksum
        const float4* src = (const float4*)(g_kv + (size_t)bh * E * E);
        float4* dst = (float4*)&kv_sm[0][0];
        #pragma unroll
        for (int i = 0; i < E*E/4/256; i++) dst[tid + i * 256] = src[tid + i * 256];
        if (tid < E) ksum_sm[tid] = g_ksum[bh * E + tid];
    }
    __syncthreads();

    const int l0 = split * P2_CHUNK;
    const int t0 = 2 * tp, t1 = 2 * tp + 1;

    for (int tile = 0; tile < P2_CHUNK / TILE2; tile++) {
        // ---- load + softmax(q) + z for 32 tokens ----
        const int l = l0 + tile * TILE2 + tok8;
        const size_t off = ((size_t)(b * L + l) * H + h) * E + (size_t)(lane8 * 8);
        float4 qa4 = *(const float4*)(queries + off);
        float4 qb4 = *(const float4*)(queries + off + 4);

        float x[8];
        x[0] = soft_logit_exp(qa4.x, inv_temp);
        x[1] = soft_logit_exp(qa4.y, inv_temp);
        x[2] = soft_logit_exp(qa4.z, inv_temp);
        x[3] = soft_logit_exp(qa4.w, inv_temp);
        x[4] = soft_logit_exp(qb4.x, inv_temp);
        x[5] = soft_logit_exp(qb4.y, inv_temp);
        x[6] = soft_logit_exp(qb4.z, inv_temp);
        x[7] = soft_logit_exp(qb4.w, inv_temp);
        float s = ((x[0]+x[1]) + (x[2]+x[3])) + ((x[4]+x[5]) + (x[6]+x[7]));
        #pragma unroll
        for (int m = 4; m >= 1; m >>= 1)
            s += __shfl_xor_sync(0xffffffffu, s, m, 8);
        float inv = 1.0f / s;
        #pragma unroll
        for (int j = 0; j < 8; j++) x[j] *= inv;

        float zd = 0.0f;
        #pragma unroll
        for (int j = 0; j < 8; j++) zd = fmaf(x[j], ksum_sm[lane8 * 8 + j], zd);
        #pragma unroll
        for (int m = 4; m >= 1; m >>= 1)
            zd += __shfl_xor_sync(0xffffffffu, zd, m, 8);
        if (lane8 == 0) z_sm[tok8] = 1.0f / (zd + EPSF);

        // offset = tok8*528 + lane8*64 : 528 % 16 == 0 -> 16B aligned
        ulonglong2* qd = (ulonglong2*)&q_dup[tok8][lane8 * 8];
        qd[0] = make_ulonglong2(dup2(x[0]), dup2(x[1]));
        qd[1] = make_ulonglong2(dup2(x[2]), dup2(x[3]));
        qd[2] = make_ulonglong2(dup2(x[4]), dup2(x[5]));
        qd[3] = make_ulonglong2(dup2(x[6]), dup2(x[7]));
        __syncwarp();   // producers & consumers of these tokens share this warp

        // ---- GEMV: 2 tokens x 4 d per thread, f32x2 on d-pairs ----
        ull a0 = 0ull, a1 = 0ull, b0 = 0ull, b1 = 0ull;
        #pragma unroll 16
        for (int e = 0; e < E; e++) {
            const ull qa = *(const ull*)&q_dup[t0][e];                // {q,q} broadcast (8B aligned)
            const ull qb = *(const ull*)&q_dup[t1][e];
            const ulonglong2 kv2 = *(const ulonglong2*)&kv_sm[e][d0]; // {kv_d0,kv_d1},{kv_d2,kv_d3}
            FFMA2(a0, qa, kv2.x, a0);
            FFMA2(a1, qa, kv2.y, a1);
            FFMA2(b0, qb, kv2.x, b0);
            FFMA2(b1, qb, kv2.y, b1);
        }
        const float z0 = z_sm[t0];
        const float z1 = z_sm[t1];
        const size_t off0 = ((size_t)(b * L + l0 + tile * TILE2 + t0) * H + h) * E + (size_t)d0;
        const size_t off1 = off0 + (size_t)(H * E);
        *(float4*)(out + off0) = make_float4(lo_f(a0)*z0, hi_f(a0)*z0, lo_f(a1)*z0, hi_f(a1)*z0);
        *(float4*)(out + off1) = make_float4(lo_f(b0)*z1, hi_f(b0)*z1, lo_f(b1)*z1, hi_f(b1)*z1);
        __syncwarp();   // protect q_dup/z_sm reuse next tile
    }
}

extern "C" void kernel_launch(void* const* d_in, const int* in_sizes, int n_in,
                              void* d_out, int out_size) {
    const float* queries = (const float*)d_in[0];
    const float* keys    = (const float*)d_in[1];
    const float* values  = (const float*)d_in[2];
    const float* delta1  = (const float*)d_in[3];
    float* out = (float*)d_out;

    (void)in_sizes; (void)n_in; (void)out_size;

    zero_scratch_kernel<<<(BH*E*E + 255)/256, 256>>>();
    phase1_kernel<<<dim3(BH, P1_SPLIT), 256>>>(keys, values, delta1);
    phase2_kernel<<<dim3(BH, P2_SPLIT), 256>>>(queries, delta1, out);
}